// round 12
// baseline (speedup 1.0000x reference)
#include <cuda_runtime.h>

#define MQ 32
#define NG 256
#define DD 128
#define QH 8                       // queries per work item
#define GRID 296                   // 2 blocks/SM on 148 SMs, perfectly balanced
#define NITEMS (NG * (MQ / QH))    // 1024 work items: (j, query-slot)

__device__ __forceinline__ unsigned long long pack2(float lo, float hi) {
    unsigned long long r;
    asm("mov.b64 %0, {%1, %2};" : "=l"(r) : "f"(lo), "f"(hi));
    return r;
}
__device__ __forceinline__ unsigned long long fma2(unsigned long long a,
                                                   unsigned long long b,
                                                   unsigned long long c) {
    unsigned long long d;
    asm("fma.rn.f32x2 %0, %1, %2, %3;" : "=l"(d) : "l"(a), "l"(b), "l"(c));
    return d;
}
__device__ __forceinline__ void unpack2(unsigned long long v, float& lo, float& hi) {
    asm("mov.b64 {%0, %1}, %2;" : "=f"(lo), "=f"(hi) : "l"(v));
}

// Persistent kernel. Block holds its (-Mp - ze) 4x8 tile in registers for the
// whole run; work items (j, 8-query slot) stream through double-buffered u
// with LDG prefetch overlapped with compute.
// pen(i,j) = 16384*ze + 0.5*( su^2 - sumMp - 16384*ze + sum|t'| ),
// t' = ua*ub - Mp - ze;  dist0 = sv/su with sv = SQ_i + SX_j - su.
__global__ __launch_bounds__(512, 2)
void jacc_pen_kernel(const float* __restrict__ qf,
                     const float* __restrict__ x,
                     const float* __restrict__ Mp,
                     const float* __restrict__ zep,
                     float* __restrict__ out) {
    const int t = threadIdx.x;
    const int w = t >> 5;
    const int l = t & 31;
    const float ze = *zep;

    __shared__ __align__(16) float ubuf[2][QH][DD];   // 8 KB double buffer
    __shared__ float part_s[QH][128];                 // 4 KB
    __shared__ float su_s[QH];
    __shared__ float sq_s[MQ];
    __shared__ float sx_s;
    __shared__ float sMw_s[16];

    // ---- Mp tile: pack (-Mp - ze) as f32x2 pairs; warp-reduce tile sum ----
    const int a0 = (t >> 4) * 4;
    const int m  = t & 15;
    const int bA = 4 * m;
    const int bB = 64 + 4 * m;
    unsigned long long nM2[4][4];
    {
        float msum = 0.0f;
        #pragma unroll
        for (int aa = 0; aa < 4; ++aa) {
            float4 m0 = *reinterpret_cast<const float4*>(Mp + (a0 + aa) * DD + bA);
            float4 m1 = *reinterpret_cast<const float4*>(Mp + (a0 + aa) * DD + bB);
            msum += ((m0.x + m0.y) + (m0.z + m0.w)) + ((m1.x + m1.y) + (m1.z + m1.w));
            nM2[aa][0] = pack2(-m0.x - ze, -m0.y - ze);
            nM2[aa][1] = pack2(-m0.z - ze, -m0.w - ze);
            nM2[aa][2] = pack2(-m1.x - ze, -m1.y - ze);
            nM2[aa][3] = pack2(-m1.z - ze, -m1.w - ze);
        }
        #pragma unroll
        for (int off = 16; off >= 1; off >>= 1)
            msum += __shfl_xor_sync(0xffffffffu, msum, off);
        if (l == 0) sMw_s[w] = msum;
    }

    // ---- SQ[i] = sum_d qf[i][d], once per block (warp w: queries w, w+16) ----
    #pragma unroll
    for (int r = 0; r < 2; ++r) {
        int i = w + r * 16;
        float4 q4 = *reinterpret_cast<const float4*>(qf + i * DD + l * 4);
        float s = (q4.x + q4.y) + (q4.z + q4.w);
        #pragma unroll
        for (int off = 16; off >= 1; off >>= 1)
            s += __shfl_xor_sync(0xffffffffu, s, off);
        if (l == 0) sq_s[i] = s;
    }

    // ---- Load first item's u into ubuf[0] ----
    int item = blockIdx.x;
    {
        int j = item >> 2, qb = (item & 3) * QH;
        int e0 = t, e1 = t + 512;
        float u0 = fmaxf(qf[(qb + (e0 >> 7)) * DD + (e0 & 127)],
                         x[j * DD + (e0 & 127)]);
        float u1 = fmaxf(qf[(qb + (e1 >> 7)) * DD + (e1 & 127)],
                         x[j * DD + (e1 & 127)]);
        ubuf[0][e0 >> 7][e0 & 127] = u0;
        ubuf[0][e1 >> 7][e1 & 127] = u1;
    }
    __syncthreads();

    float sm = 0.0f;
    #pragma unroll
    for (int k = 0; k < 16; ++k) sm += sMw_s[k];

    int cur = 0;
    #pragma unroll 1
    for (; item < NITEMS; item += GRID) {
        const int j  = item >> 2;
        const int qb = (item & 3) * QH;
        const int nitem = item + GRID;

        // ---- prefetch next item's inputs (LDG overlapped with compute) ----
        float pq0 = 0.0f, pq1 = 0.0f, px0 = 0.0f, px1 = 0.0f;
        if (nitem < NITEMS) {
            int nj = nitem >> 2, nqb = (nitem & 3) * QH;
            int e0 = t, e1 = t + 512;
            pq0 = qf[(nqb + (e0 >> 7)) * DD + (e0 & 127)];
            px0 = x[nj * DD + (e0 & 127)];
            pq1 = qf[(nqb + (e1 >> 7)) * DD + (e1 & 127)];
            px1 = x[nj * DD + (e1 & 127)];
        }

        // ---- su per query (warps 0-7, from ubuf); SX_j (warp 8) ----
        if (w < QH) {
            float4 v = *reinterpret_cast<const float4*>(&ubuf[cur][w][l * 4]);
            float s = (v.x + v.y) + (v.z + v.w);
            #pragma unroll
            for (int off = 16; off >= 1; off >>= 1)
                s += __shfl_xor_sync(0xffffffffu, s, off);
            if (l == 0) su_s[w] = s;
        } else if (w == 8) {
            float4 v = *reinterpret_cast<const float4*>(x + j * DD + l * 4);
            float s = (v.x + v.y) + (v.z + v.w);
            #pragma unroll
            for (int off = 16; off >= 1; off >>= 1)
                s += __shfl_xor_sync(0xffffffffu, s, off);
            if (l == 0) sx_s = s;
        }

        // ---- penalty: 2 passes of 4 queries (R10 inner form) ----
        const float* ua_p = &ubuf[cur][0][a0];
        const float* ub_p = &ubuf[cur][0][bA];
        float* st_p = &part_s[0][t >> 2];
        #pragma unroll
        for (int ig = 0; ig < QH; ig += 4) {
            float wv[4];
            #pragma unroll
            for (int s = 0; s < 4; ++s) {
                const float* uap = ua_p + s * DD;
                const float* ubp = ub_p + s * DD;
                float4 va = *reinterpret_cast<const float4*>(uap);
                ulonglong2 c0 = *reinterpret_cast<const ulonglong2*>(ubp);
                ulonglong2 c1 = *reinterpret_cast<const ulonglong2*>(ubp + 64);
                unsigned long long ub2[4] = {c0.x, c0.y, c1.x, c1.y};
                float ua[4] = {va.x, va.y, va.z, va.w};

                float acc[4] = {0.0f, 0.0f, 0.0f, 0.0f};
                #pragma unroll
                for (int aa = 0; aa < 4; ++aa) {
                    unsigned long long ua2 = pack2(ua[aa], ua[aa]);
                    #pragma unroll
                    for (int bpp = 0; bpp < 4; ++bpp) {
                        float lo, hi;
                        unpack2(fma2(ua2, ub2[bpp], nM2[aa][bpp]), lo, hi);
                        acc[bpp] += fabsf(lo);          // FADD with |src|
                        acc[(bpp + 2) & 3] += fabsf(hi);
                    }
                }
                wv[s] = (acc[0] + acc[1]) + (acc[2] + acc[3]);
            }
            #pragma unroll
            for (int s = 0; s < 4; ++s)
                wv[s] += __shfl_down_sync(0xffffffffu, wv[s], 2, 4);
            #pragma unroll
            for (int s = 0; s < 4; ++s)
                wv[s] += __shfl_down_sync(0xffffffffu, wv[s], 1, 4);
            if ((t & 3) == 0) {
                #pragma unroll
                for (int s = 0; s < 4; ++s)
                    st_p[s * 128] = wv[s];
            }
            ua_p += 4 * DD;
            ub_p += 4 * DD;
            st_p += 4 * 128;
        }

        __syncthreads();

        // ---- epilogue: warps 0-7 finish their query; write output ----
        if (w < QH) {
            float p = (part_s[w][l]      + part_s[w][l + 32])
                    + (part_s[w][l + 64] + part_s[w][l + 96]);
            #pragma unroll
            for (int off = 16; off >= 1; off >>= 1)
                p += __shfl_xor_sync(0xffffffffu, p, off);
            if (l == 0) {
                float su = su_s[w];
                float sv = sq_s[qb + w] + sx_s - su;
                const float NE = (float)(DD * DD);  // 16384
                float pen = NE * ze + 0.5f * ((su * su - sm - NE * ze) + p);
                out[(qb + w) * NG + j] = sv / su - 0.001f * pen;
            }
        }

        // ---- store next item's u into the other buffer ----
        if (nitem < NITEMS) {
            int e0 = t, e1 = t + 512;
            ubuf[cur ^ 1][e0 >> 7][e0 & 127] = fmaxf(pq0, px0);
            ubuf[cur ^ 1][e1 >> 7][e1 & 127] = fmaxf(pq1, px1);
        }
        __syncthreads();
        cur ^= 1;
    }
}

extern "C" void kernel_launch(void* const* d_in, const int* in_sizes, int n_in,
                              void* d_out, int out_size) {
    const float* qf = (const float*)d_in[0];   // (32, 128)
    const float* x  = (const float*)d_in[1];   // (256, 128)
    const float* Mp = (const float*)d_in[2];   // (128, 128)
    const float* ze = (const float*)d_in[3];   // scalar
    float* out = (float*)d_out;                // (32, 256)
    (void)in_sizes; (void)n_in; (void)out_size;

    jacc_pen_kernel<<<GRID, 512>>>(qf, x, Mp, ze, out);
}